// round 16
// baseline (speedup 1.0000x reference)
#include <cuda_runtime.h>
#include <cuda_fp16.h>
#include <cstdint>

// Problem constants
#define BATCH 8
#define CDIM 512
#define LDIM 4096
#define HEADS 8
#define DHEAD 64
#define HID 512            // HEADS*DHEAD
#define QKV_ROWS 1536      // 3*HID
#define KV_ROWS 1024       // k,v only
#define CSPLIT 32          // n-splits for context partials

// ---------------------------------------------------------------------------
// Scratch (device globals; no allocation allowed)
// ---------------------------------------------------------------------------
__device__ float g_kv[(size_t)BATCH * KV_ROWS * LDIM];      // k rows 0..511 (RAW), v rows 512..1023
__device__ __half g_xt1[(size_t)BATCH * LDIM * CDIM];       // x^T, 1 fp16 limb
__device__ __half g_w1[(size_t)KV_ROWS * CDIM];             // W_kv, 1 limb
__device__ __half g_wqT1[(size_t)CDIM * HID];               // Wq^T limb 1
__device__ __half g_wqT2[(size_t)CDIM * HID];               // Wq^T limb 2
__device__ float g_rmax[(size_t)BATCH * HID];               // k row max
__device__ float g_rinv[(size_t)BATCH * HID];               // 1 / sum(exp(k-m))
__device__ float g_part[(size_t)CSPLIT * BATCH * HEADS * DHEAD * DHEAD];
__device__ float g_ctx[(size_t)BATCH * HEADS * DHEAD * DHEAD];
__device__ __half g_M1[(size_t)BATCH * HID * HID];          // M limbs
__device__ __half g_M2[(size_t)BATCH * HID * HID];
__device__ __half g_N1[(size_t)BATCH * HID * CDIM];         // N = M @ Wq limbs
__device__ __half g_N2[(size_t)BATCH * HID * CDIM];

// ---------------------------------------------------------------------------
// PTX helpers (baseline sm_103 — mma.sync fp16 only)
// ---------------------------------------------------------------------------
__device__ __forceinline__ uint32_t smem_to_u32(const void* smem_ptr) {
    uint32_t addr;
    asm("{ .reg .u64 tmp; cvta.to.shared.u64 tmp, %1; cvt.u32.u64 %0, tmp; }"
        : "=r"(addr) : "l"(smem_ptr));
    return addr;
}

#define SMEM_SWIZZLE_128B(byte_offset) \
    ((uint32_t)(byte_offset) ^ ((((uint32_t)(byte_offset)) >> 3) & 0x70u))

__device__ __forceinline__ void cp_async16(uint32_t dst, const void* src) {
    asm volatile("cp.async.cg.shared.global [%0], [%1], 16;"
                 :: "r"(dst), "l"(src) : "memory");
}
#define CP_ASYNC_COMMIT() asm volatile("cp.async.commit_group;" ::: "memory")
#define CP_ASYNC_WAIT(n)  asm volatile("cp.async.wait_group %0;" :: "n"(n) : "memory")

__device__ __forceinline__ void ldsm4(uint32_t* r, uint32_t addr) {
    asm volatile("ldmatrix.sync.aligned.m8n8.x4.shared.b16 {%0,%1,%2,%3}, [%4];"
                 : "=r"(r[0]), "=r"(r[1]), "=r"(r[2]), "=r"(r[3]) : "r"(addr));
}

__device__ __forceinline__ void mma_f16(float* c, const uint32_t* a, const uint32_t* b) {
    asm volatile(
        "mma.sync.aligned.m16n8k16.row.col.f32.f16.f16.f32 "
        "{%0,%1,%2,%3}, {%4,%5,%6,%7}, {%8,%9}, {%0,%1,%2,%3};"
        : "+f"(c[0]), "+f"(c[1]), "+f"(c[2]), "+f"(c[3])
        : "r"(a[0]), "r"(a[1]), "r"(a[2]), "r"(a[3]), "r"(b[0]), "r"(b[1]));
}

#define CHUNKS_PER_TILE 8    // K=512 / BK=64

// ---------------------------------------------------------------------------
// 1-term persistent fp16 GEMM: C = A1 @ B1^T (+bias).
// 256 threads (8 warps, 4x2 grid, warp tile 32x64), tile 128m x 128n.
// 3-stage cp.async ring (32KB/stage, 96KB/CTA -> 2 CTAs/SM = 16 warps/SM).
// Single barrier per chunk (3-stage ring proves stage (k+2)%3 free).
// ---------------------------------------------------------------------------
#define S1_STAGE 32768
#define S1_OFF_A 0
#define S1_OFF_B 16384
#define S1_SMEM (3 * S1_STAGE)

__global__ __launch_bounds__(256, 2)
void gemm1t_persistent(const __half* __restrict__ A1,
                       const __half* __restrict__ B1,
                       float* __restrict__ C,
                       int ntm, int ntn, int nb, int N, int K,
                       long long sA, long long sB, long long sC,
                       const float* __restrict__ bias)
{
    extern __shared__ char smem[];
    const uint32_t sbase = smem_to_u32(smem);

    const int tid = threadIdx.x;
    const int wid = tid >> 5;
    const int lane = tid & 31;
    const int warp_m = wid >> 1;       // 0..3 (32 rows each)
    const int warp_n = wid & 1;        // 0..1 (64 cols each)

    const int ntiles = ntm * ntn * nb;
    const int my_ntiles = (ntiles - (int)blockIdx.x + (int)gridDim.x - 1) / (int)gridDim.x;
    if (my_ntiles <= 0) return;
    const int my_nchunks = my_ntiles * CHUNKS_PER_TILE;

    auto load_chunk = [&](int k) {
        const int t = k >> 3;
        const int tile_lin = (int)blockIdx.x + t * (int)gridDim.x;
        if (tile_lin >= ntiles) { CP_ASYNC_COMMIT(); return; }
        const int nx = tile_lin % ntn;
        const int rest = tile_lin / ntn;
        const int my = rest % ntm;
        const int b = rest / ntm;
        const int bm = my << 7;        // 128-row tiles
        const int bn = nx << 7;        // 128-col tiles
        const int k0 = (k & 7) << 6;
        const __half* pA = A1 + (long long)b * sA;
        const __half* pB = B1 + (long long)b * sB;
        const uint32_t sb = sbase + (uint32_t)(k % 3) * S1_STAGE;
        // A: 128 rows x 8 granules = 1024; B same. 256 threads -> 4 iters each.
#pragma unroll
        for (int it = 0; it < 4; it++) {
            const int g = it * 256 + tid;
            const int row = g >> 3;
            const int gr = g & 7;
            const uint32_t sw = SMEM_SWIZZLE_128B(row * 128 + gr * 16);
            cp_async16(sb + S1_OFF_A + sw, pA + (long long)(bm + row) * K + k0 + gr * 8);
            cp_async16(sb + S1_OFF_B + sw, pB + (long long)(bn + row) * K + k0 + gr * 8);
        }
        CP_ASYNC_COMMIT();
    };

    float acc[2][8][4];
#pragma unroll
    for (int i = 0; i < 2; i++)
#pragma unroll
        for (int j = 0; j < 8; j++)
#pragma unroll
            for (int r = 0; r < 4; r++) acc[i][j][r] = 0.0f;

    load_chunk(0);
    load_chunk(1);

    for (int k = 0; k < my_nchunks; k++) {
        CP_ASYNC_WAIT(1);
        __syncthreads();          // single barrier per chunk

        const uint32_t sb = sbase + (uint32_t)(k % 3) * S1_STAGE;
#pragma unroll
        for (int ks = 0; ks < 4; ks++) {
            uint32_t b1r[16];
#pragma unroll
            for (int p = 0; p < 4; p++) {
                const int r = warp_n * 64 + p * 16 + ((lane >> 4) & 1) * 8 + (lane & 7);
                const int cb = ks * 32 + ((lane >> 3) & 1) * 16;
                ldsm4(b1r + p * 4, sb + S1_OFF_B + SMEM_SWIZZLE_128B(r * 128 + cb));
            }
#pragma unroll
            for (int i = 0; i < 2; i++) {
                const int r = warp_m * 32 + i * 16 + ((lane >> 3) & 1) * 8 + (lane & 7);
                const int cb = ks * 32 + ((lane >> 4) & 1) * 16;
                uint32_t a1[4];
                ldsm4(a1, sb + S1_OFF_A + SMEM_SWIZZLE_128B(r * 128 + cb));
#pragma unroll
                for (int j = 0; j < 8; j++)
                    mma_f16(acc[i][j], a1, b1r + (j >> 1) * 4 + (j & 1) * 2);
            }
        }

        load_chunk(k + 2);        // writes stage (k+2)%3 == (k-1)%3: safe

        if ((k & 7) == 7) {
            const int t = k >> 3;
            const int tile_lin = (int)blockIdx.x + t * (int)gridDim.x;
            const int nx = tile_lin % ntn;
            const int rest = tile_lin / ntn;
            const int my = rest % ntm;
            const int b = rest / ntm;
            const int bm = my << 7;
            const int bn = nx << 7;
            float* pC = C + (long long)b * sC;
#pragma unroll
            for (int i = 0; i < 2; i++) {
                const int m0 = bm + warp_m * 32 + i * 16 + (lane >> 2);
                const float bv0 = bias ? bias[m0] : 0.0f;
                const float bv1 = bias ? bias[m0 + 8] : 0.0f;
#pragma unroll
                for (int j = 0; j < 8; j++) {
                    const int n0 = bn + warp_n * 64 + j * 8 + (lane & 3) * 2;
                    float2 v0, v1;
                    v0.x = acc[i][j][0] + bv0;  v0.y = acc[i][j][1] + bv0;
                    v1.x = acc[i][j][2] + bv1;  v1.y = acc[i][j][3] + bv1;
                    *(float2*)(pC + (long long)m0 * N + n0) = v0;
                    *(float2*)(pC + (long long)(m0 + 8) * N + n0) = v1;
                    acc[i][j][0] = 0.0f; acc[i][j][1] = 0.0f;
                    acc[i][j][2] = 0.0f; acc[i][j][3] = 0.0f;
                }
            }
        }
    }
}

// ---------------------------------------------------------------------------
// General multi-limb persistent GEMM (tiny N = M @ Wq only, 3-term,
// 2-limb fp16 output). 128 threads, tile 64x128, 2-stage. As round 15.
// ---------------------------------------------------------------------------
#define STAGE_BYTES 49152
#define OFF_A1 0
#define OFF_A2 8192
#define OFF_B1 16384
#define OFF_B2 32768
#define GEMM_SMEM (2 * STAGE_BYTES)

__global__ __launch_bounds__(128, 2)
void mma_gemm_persistent(const __half* __restrict__ A1,
                         const __half* __restrict__ A2,
                         const __half* __restrict__ B1,
                         const __half* __restrict__ B2,
                         float* __restrict__ C,
                         int ntm, int ntn, int nb, int N, int K,
                         long long sA, long long sB, long long sC,
                         const float* __restrict__ bias,
                         __half* __restrict__ O1,
                         __half* __restrict__ O2)
{
    extern __shared__ char smem[];
    const uint32_t sbase = smem_to_u32(smem);

    const int tid = threadIdx.x;
    const int wid = tid >> 5;
    const int lane = tid & 31;
    const int warp_m = wid >> 1;
    const int warp_n = wid & 1;
    const bool has_a2 = (A2 != nullptr);
    const bool has_b2 = (B2 != nullptr);

    const int ntiles = ntm * ntn * nb;
    const int my_ntiles = (ntiles - (int)blockIdx.x + (int)gridDim.x - 1) / (int)gridDim.x;
    if (my_ntiles <= 0) return;
    const int my_nchunks = my_ntiles * CHUNKS_PER_TILE;

    auto load_chunk = [&](int k) {
        const int t = k >> 3;
        const int tile_lin = (int)blockIdx.x + t * (int)gridDim.x;
        if (tile_lin >= ntiles) { CP_ASYNC_COMMIT(); return; }
        const int nx = tile_lin % ntn;
        const int rest = tile_lin / ntn;
        const int my = rest % ntm;
        const int b = rest / ntm;
        const int bm = my << 6;
        const int bn = nx << 7;
        const int k0 = (k & 7) << 6;
        const __half* pA1 = A1 + (long long)b * sA;
        const __half* pB1 = B1 + (long long)b * sB;
        const uint32_t sb = sbase + (uint32_t)(k & 1) * STAGE_BYTES;
#pragma unroll
        for (int it = 0; it < 4; it++) {
            const int g = it * 128 + tid;
            const int row = g >> 3;
            const int gr = g & 7;
            const uint32_t sw = SMEM_SWIZZLE_128B(row * 128 + gr * 16);
            cp_async16(sb + OFF_A1 + sw, pA1 + (long long)(bm + row) * K + k0 + gr * 8);
        }
        if (has_a2) {
            const __half* pA2 = A2 + (long long)b * sA;
#pragma unroll
            for (int it = 0; it < 4; it++) {
                const int g = it * 128 + tid;
                const int row = g >> 3;
                const int gr = g & 7;
                const uint32_t sw = SMEM_SWIZZLE_128B(row * 128 + gr * 16);
                cp_async16(sb + OFF_A2 + sw, pA2 + (long long)(bm + row) * K + k0 + gr * 8);
            }
        }
#pragma unroll
        for (int it = 0; it < 8; it++) {
            const int g = it * 128 + tid;
            const int row = g >> 3;
            const int gr = g & 7;
            const uint32_t sw = SMEM_SWIZZLE_128B(row * 128 + gr * 16);
            cp_async16(sb + OFF_B1 + sw, pB1 + (long long)(bn + row) * K + k0 + gr * 8);
        }
        if (has_b2) {
            const __half* pB2 = B2 + (long long)b * sB;
#pragma unroll
            for (int it = 0; it < 8; it++) {
                const int g = it * 128 + tid;
                const int row = g >> 3;
                const int gr = g & 7;
                const uint32_t sw = SMEM_SWIZZLE_128B(row * 128 + gr * 16);
                cp_async16(sb + OFF_B2 + sw, pB2 + (long long)(bn + row) * K + k0 + gr * 8);
            }
        }
        CP_ASYNC_COMMIT();
    };

    float acc[2][8][4];
#pragma unroll
    for (int i = 0; i < 2; i++)
#pragma unroll
        for (int j = 0; j < 8; j++)
#pragma unroll
            for (int r = 0; r < 4; r++) acc[i][j][r] = 0.0f;

    load_chunk(0);
    load_chunk(1);

    for (int k = 0; k < my_nchunks; k++) {
        CP_ASYNC_WAIT(1);
        __syncthreads();

        const uint32_t sb = sbase + (uint32_t)(k & 1) * STAGE_BYTES;
#pragma unroll
        for (int ks = 0; ks < 4; ks++) {
            uint32_t b1r[16];
#pragma unroll
            for (int p = 0; p < 4; p++) {
                const int r = warp_n * 64 + p * 16 + ((lane >> 4) & 1) * 8 + (lane & 7);
                const int cb = ks * 32 + ((lane >> 3) & 1) * 16;
                ldsm4(b1r + p * 4, sb + OFF_B1 + SMEM_SWIZZLE_128B(r * 128 + cb));
            }
            uint32_t b2r[16];
            if (has_b2) {
#pragma unroll
                for (int p = 0; p < 4; p++) {
                    const int r = warp_n * 64 + p * 16 + ((lane >> 4) & 1) * 8 + (lane & 7);
                    const int cb = ks * 32 + ((lane >> 3) & 1) * 16;
                    ldsm4(b2r + p * 4, sb + OFF_B2 + SMEM_SWIZZLE_128B(r * 128 + cb));
                }
            }
#pragma unroll
            for (int i = 0; i < 2; i++) {
                const int r = warp_m * 32 + i * 16 + ((lane >> 3) & 1) * 8 + (lane & 7);
                const int cb = ks * 32 + ((lane >> 4) & 1) * 16;
                const uint32_t adr = sb + OFF_A1 + SMEM_SWIZZLE_128B(r * 128 + cb);
                uint32_t a1[4];
                ldsm4(a1, adr);
#pragma unroll
                for (int j = 0; j < 8; j++)
                    mma_f16(acc[i][j], a1, b1r + (j >> 1) * 4 + (j & 1) * 2);
                if (has_a2) {
                    uint32_t a2[4];
                    ldsm4(a2, adr + (OFF_A2 - OFF_A1));
#pragma unroll
                    for (int j = 0; j < 8; j++)
                        mma_f16(acc[i][j], a2, b1r + (j >> 1) * 4 + (j & 1) * 2);
                }
                if (has_b2) {
#pragma unroll
                    for (int j = 0; j < 8; j++)
                        mma_f16(acc[i][j], a1, b2r + (j >> 1) * 4 + (j & 1) * 2);
                }
            }
        }
        __syncthreads();
        load_chunk(k + 2);

        if ((k & 7) == 7) {
            const int t = k >> 3;
            const int tile_lin = (int)blockIdx.x + t * (int)gridDim.x;
            const int nx = tile_lin % ntn;
            const int rest = tile_lin / ntn;
            const int my = rest % ntm;
            const int b = rest / ntm;
            const int bm = my << 6;
            const int bn = nx << 7;
            if (O1 == nullptr) {
                float* pC = C + (long long)b * sC;
#pragma unroll
                for (int i = 0; i < 2; i++) {
                    const int m0 = bm + warp_m * 32 + i * 16 + (lane >> 2);
                    const float bv0 = bias ? bias[m0] : 0.0f;
                    const float bv1 = bias ? bias[m0 + 8] : 0.0f;
#pragma unroll
                    for (int j = 0; j < 8; j++) {
                        const int n0 = bn + warp_n * 64 + j * 8 + (lane & 3) * 2;
                        float2 v0, v1;
                        v0.x = acc[i][j][0] + bv0;  v0.y = acc[i][j][1] + bv0;
                        v1.x = acc[i][j][2] + bv1;  v1.y = acc[i][j][3] + bv1;
                        *(float2*)(pC + (long long)m0 * N + n0) = v0;
                        *(float2*)(pC + (long long)(m0 + 8) * N + n0) = v1;
                        acc[i][j][0] = 0.0f; acc[i][j][1] = 0.0f;
                        acc[i][j][2] = 0.0f; acc[i][j][3] = 0.0f;
                    }
                }
            } else {
                __half* p1 = O1 + (long long)b * sC;
                __half* p2 = O2 + (long long)b * sC;
#pragma unroll
                for (int i = 0; i < 2; i++) {
                    const int m0 = bm + warp_m * 32 + i * 16 + (lane >> 2);
#pragma unroll
                    for (int j = 0; j < 8; j++) {
                        const int n0 = bn + warp_n * 64 + j * 8 + (lane & 3) * 2;
#pragma unroll
                        for (int r = 0; r < 4; r++) {
                            const int mm = m0 + (r >> 1) * 8;
                            const int nn = n0 + (r & 1);
                            const float v = acc[i][j][r];
                            const __half h1 = __float2half_rn(v);
                            p1[(long long)mm * N + nn] = h1;
                            p2[(long long)mm * N + nn] = __float2half_rn(v - __half2float(h1));
                            acc[i][j][r] = 0.0f;
                        }
                    }
                }
            }
        }
    }
}

// ---------------------------------------------------------------------------
// Transpose + fp16 convert (1 limb): in fp32 [R, L] -> out [L, R]
// ---------------------------------------------------------------------------
__global__ __launch_bounds__(256) void transpose_cvt1_kernel(
    const float* __restrict__ in, __half* __restrict__ out,
    int R, int L, long long inStride, long long outStride)
{
    const int b = blockIdx.z;
    in += (long long)b * inStride;
    out += (long long)b * outStride;

    __shared__ float t[32][33];
    const int r0 = blockIdx.y * 32;
    const int c0 = blockIdx.x * 32;
    const int tx = threadIdx.x & 31;
    const int ty = threadIdx.x >> 5;

#pragma unroll
    for (int i = 0; i < 4; i++)
        t[ty + i * 8][tx] = in[(long long)(r0 + ty + i * 8) * L + c0 + tx];
    __syncthreads();
#pragma unroll
    for (int i = 0; i < 4; i++) {
        const float v = t[tx][ty + i * 8];
        out[(long long)(c0 + ty + i * 8) * R + r0 + tx] = __float2half_rn(v);
    }
}

// Transpose + fp16 2-limb split: in fp32 [R, L] -> limbs [L, R]
__global__ __launch_bounds__(256) void transpose_cvt2_kernel(
    const float* __restrict__ in,
    __half* __restrict__ o1, __half* __restrict__ o2, int R, int L)
{
    __shared__ float t[32][33];
    const int r0 = blockIdx.y * 32;
    const int c0 = blockIdx.x * 32;
    const int tx = threadIdx.x & 31;
    const int ty = threadIdx.x >> 5;

#pragma unroll
    for (int i = 0; i < 4; i++)
        t[ty + i * 8][tx] = in[(long long)(r0 + ty + i * 8) * L + c0 + tx];
    __syncthreads();
#pragma unroll
    for (int i = 0; i < 4; i++) {
        const float v = t[tx][ty + i * 8];
        const __half h1 = __float2half_rn(v);
        const long long o = (long long)(c0 + ty + i * 8) * R + r0 + tx;
        o1[o] = h1;
        o2[o] = __float2half_rn(v - __half2float(h1));
    }
}

// Plain fp16 convert (1 limb)
__global__ __launch_bounds__(256) void cvt1_kernel(
    const float* __restrict__ in, __half* __restrict__ o1, int n)
{
    const int i = blockIdx.x * blockDim.x + threadIdx.x;
    if (i < n) o1[i] = __float2half_rn(in[i]);
}

// ---------------------------------------------------------------------------
// Row stats for softmax (READ-ONLY): max + 1/sum(exp(k-m)) per k row.
// k rows are rows 0..511 of g_kv per batch; k left RAW in memory.
// ---------------------------------------------------------------------------
__global__ __launch_bounds__(256) void rowstat_kernel()
{
    const int row = blockIdx.x;           // 0..BATCH*512-1
    const int b = row >> 9;
    const int r = row & 511;
    const float* p = g_kv + (long long)b * KV_ROWS * LDIM + (long long)r * LDIM;

    const int tid = threadIdx.x;
    __shared__ float red[256];

    float4 v[4];
#pragma unroll
    for (int i = 0; i < 4; i++)
        v[i] = *(const float4*)(p + i * 1024 + tid * 4);

    float vmax = -1e30f;
#pragma unroll
    for (int i = 0; i < 4; i++)
        vmax = fmaxf(vmax, fmaxf(fmaxf(v[i].x, v[i].y), fmaxf(v[i].z, v[i].w)));
    red[tid] = vmax;
    __syncthreads();
    for (int s = 128; s > 0; s >>= 1) {
        if (tid < s) red[tid] = fmaxf(red[tid], red[tid + s]);
        __syncthreads();
    }
    vmax = red[0];
    __syncthreads();

    float lsum = 0.0f;
#pragma unroll
    for (int i = 0; i < 4; i++) {
        lsum += expf(v[i].x - vmax) + expf(v[i].y - vmax)
              + expf(v[i].z - vmax) + expf(v[i].w - vmax);
    }
    red[tid] = lsum;
    __syncthreads();
    for (int s = 128; s > 0; s >>= 1) {
        if (tid < s) red[tid] += red[tid + s];
        __syncthreads();
    }
    if (tid == 0) {
        g_rmax[row] = vmax;
        g_rinv[row] = 1.0f / red[0];
    }
}

// ---------------------------------------------------------------------------
// Context partials: softmax applied INLINE on k load (each k element is
// consumed by exactly one block, so no write-back pass is needed).
// ---------------------------------------------------------------------------
__global__ __launch_bounds__(256) void context_partial_kernel()
{
    const int split = blockIdx.x;
    const int bh = blockIdx.y;
    const int b = bh >> 3, h = bh & 7;

    const float* kbase = g_kv + (long long)b * KV_ROWS * LDIM + (long long)(h * DHEAD) * LDIM;
    const float* vbase = g_kv + (long long)b * KV_ROWS * LDIM + (long long)(HID + h * DHEAD) * LDIM;

    __shared__ float Ks[64][65];
    __shared__ float Vs[64][65];
    __shared__ float sm_m[64], sm_i[64];

    const int tid = threadIdx.x;
    if (tid < 64) {
        const int row = b * HID + h * DHEAD + tid;
        sm_m[tid] = g_rmax[row];
        sm_i[tid] = g_rinv[row];
    }
    __syncthreads();

    const int td = (tid >> 4) * 4;
    const int te = (tid & 15) * 4;

    float acc[4][4];
#pragma unroll
    for (int i = 0; i < 4; i++)
#pragma unroll
        for (int j = 0; j < 4; j++) acc[i][j] = 0.0f;

    const int chunk = LDIM / CSPLIT;
    for (int sub = 0; sub < chunk / 64; sub++) {
        const int n0 = split * chunk + sub * 64;
        for (int i = tid; i < 1024; i += 256) {
            const int r = i >> 4, c = (i & 15) * 4;
            const float m = sm_m[r], s = sm_i[r];
            float4 kv = *(const float4*)(kbase + (long long)r * LDIM + n0 + c);
            Ks[r][c]     = expf(kv.x - m) * s;
            Ks[r][c + 1] = expf(kv.y - m) * s;
            Ks[r][c + 2] = expf(kv.z - m) * s;
            Ks[r][c + 3] = expf(kv.w - m) * s;
            float4 vv = *(const float4*)(vbase + (long long)r * LDIM + n0 + c);
            Vs[r][c] = vv.x; Vs[r][c + 1] = vv.y; Vs[r][c + 2] = vv.z; Vs[r][c + 3] = vv.w;
        }
        __syncthreads();

#pragma unroll 8
        for (int n = 0; n < 64; n++) {
            float kr[4], vr[4];
#pragma unroll
            for (int i = 0; i < 4; i++) kr[i] = Ks[td + i][n];
#pragma unroll
            for (int j = 0; j < 4; j++) vr[j] = Vs[te + j][n];
#pragma unroll
            for (int i = 0; i < 4; i++)
#pragma unroll
                for (int j = 0; j < 4; j++)
                    acc[i][j] = fmaf(kr[i], vr[j], acc[i][j]);
        }
        __syncthreads();
    }

    float* pout = g_part + ((long long)split * 64 + bh) * (DHEAD * DHEAD);
#pragma unroll
    for (int i = 0; i < 4; i++)
#pragma unroll
        for (int j = 0; j < 4; j++)
            pout[(td + i) * DHEAD + (te + j)] = acc[i][j];
}

__global__ __launch_bounds__(256) void reduce_ctx_kernel()
{
    const int i = blockIdx.x * blockDim.x + threadIdx.x;
    const int total = BATCH * HEADS * DHEAD * DHEAD;
    if (i < total) {
        float s = 0.0f;
#pragma unroll
        for (int sp = 0; sp < CSPLIT; sp++)
            s += g_part[(long long)sp * total + i];
        g_ctx[i] = s;
    }
}

// fold: writes 2-limb fp16 M directly
__global__ __launch_bounds__(256) void fold_kernel(const float* __restrict__ w_out)
{
    const int oc = blockIdx.x;
    const int bh = blockIdx.y;
    const int b = bh >> 3, h = bh & 7;

    __shared__ float cs[64][65];
    __shared__ float ws[64][65];

    const int tid = threadIdx.x;
    for (int i = tid; i < 4096; i += 256) {
        const int d = i >> 6, e = i & 63;
        cs[d][e] = g_ctx[((long long)bh * 64 + d) * 64 + e];
    }
    for (int i = tid; i < 4096; i += 256) {
        const int r = i >> 6, e = i & 63;
        ws[r][e] = w_out[(long long)(oc * 64 + r) * CDIM + h * 64 + e];
    }
    __syncthreads();

    const int d = tid & 63;
    const int r0 = (tid >> 6) * 16;
    for (int rr = 0; rr < 16; rr++) {
        float s = 0.0f;
#pragma unroll 8
        for (int e = 0; e < 64; e++)
            s = fmaf(ws[r0 + rr][e], cs[d][e], s);
        const long long o = ((long long)b * HID + oc * 64 + r0 + rr) * HID + h * 64 + d;
        const __half h1 = __float2half_rn(s);
        g_M1[o] = h1;
        g_M2[o] = __float2half_rn(s - __half2float(h1));
    }
}

// ---------------------------------------------------------------------------
extern "C" void kernel_launch(void* const* d_in, const int* in_sizes, int n_in,
                              void* d_out, int out_size)
{
    const float* x     = (const float*)d_in[0];   // [8, 512, 4096]
    const float* w_qkv = (const float*)d_in[1];   // [1536, 512]
    const float* w_out = (const float*)d_in[2];   // [512, 512]
    const float* b_out = (const float*)d_in[3];   // [512]
    float* out = (float*)d_out;                   // [8, 512, 4096]

    float *p_kv;
    __half *p_xt1, *p_w1, *p_wqT1, *p_wqT2, *p_M1, *p_M2, *p_N1, *p_N2;
    cudaGetSymbolAddress((void**)&p_kv, g_kv);
    cudaGetSymbolAddress((void**)&p_xt1, g_xt1);
    cudaGetSymbolAddress((void**)&p_w1, g_w1);
    cudaGetSymbolAddress((void**)&p_wqT1, g_wqT1);
    cudaGetSymbolAddress((void**)&p_wqT2, g_wqT2);
    cudaGetSymbolAddress((void**)&p_M1, g_M1);
    cudaGetSymbolAddress((void**)&p_M2, g_M2);
    cudaGetSymbolAddress((void**)&p_N1, g_N1);
    cudaGetSymbolAddress((void**)&p_N2, g_N2);

    int nsm = 148;
    cudaDeviceGetAttribute(&nsm, cudaDevAttrMultiProcessorCount, 0);

    cudaFuncSetAttribute(gemm1t_persistent,
                         cudaFuncAttributeMaxDynamicSharedMemorySize, S1_SMEM);
    cudaFuncSetAttribute(mma_gemm_persistent,
                         cudaFuncAttributeMaxDynamicSharedMemorySize, GEMM_SMEM);

    // 0) fp16 converts: W_kv (1 limb), x^T (1 limb), Wq^T (2 limbs)
    cvt1_kernel<<<(KV_ROWS * CDIM + 255) / 256, 256>>>(
        w_qkv + (size_t)HID * CDIM, p_w1, KV_ROWS * CDIM);
    transpose_cvt1_kernel<<<dim3(LDIM / 32, CDIM / 32, BATCH), 256>>>(
        x, p_xt1, CDIM, LDIM, (long long)CDIM * LDIM, (long long)LDIM * CDIM);
    transpose_cvt2_kernel<<<dim3(CDIM / 32, HID / 32, 1), 256>>>(
        w_qkv, p_wqT1, p_wqT2, HID, CDIM);

    // 1) kv = W_kv @ x  (1-term fp16, 16 warps/SM)
    gemm1t_persistent<<<2 * nsm, 256, S1_SMEM>>>(
        p_w1, p_xt1, p_kv,
        KV_ROWS / 128, LDIM / 128, BATCH, LDIM, CDIM,
        0LL, (long long)LDIM * CDIM, (long long)KV_ROWS * LDIM, nullptr);

    // 2) softmax row stats only (k stays raw; applied inline in context)
    rowstat_kernel<<<BATCH * HID, 256>>>();

    // 3) context partials (inline softmax) + deterministic reduce
    context_partial_kernel<<<dim3(CSPLIT, BATCH * HEADS), 256>>>();
    {
        const int total = BATCH * HEADS * DHEAD * DHEAD;
        reduce_ctx_kernel<<<(total + 255) / 256, 256>>>();
    }

    // 4) fold w_out with context -> 2-limb fp16 M
    fold_kernel<<<dim3(8, BATCH * HEADS), 256>>>(w_out);

    // 5) N = M @ Wq  (3-term fp16; tiny, keeps this link near-exact)
    mma_gemm_persistent<<<2 * nsm, 128, GEMM_SMEM>>>(
        p_M1, p_M2, p_wqT1, p_wqT2, nullptr,
        HID / 64, CDIM / 128, BATCH, CDIM, HID,
        (long long)HID * HID, 0LL, (long long)HID * CDIM, nullptr,
        p_N1, p_N2);

    // 6) out = N @ x + b_out  (1-term fp16, 16 warps/SM)
    gemm1t_persistent<<<2 * nsm, 256, S1_SMEM>>>(
        p_N1, p_xt1, out,
        HID / 128, LDIM / 128, BATCH, LDIM, CDIM,
        (long long)HID * CDIM, (long long)LDIM * CDIM, (long long)HID * LDIM, b_out);
}

// round 17
// speedup vs baseline: 1.0389x; 1.0389x over previous
#include <cuda_runtime.h>
#include <cuda_fp16.h>
#include <cstdint>

// Problem constants
#define BATCH 8
#define CDIM 512
#define LDIM 4096
#define HEADS 8
#define DHEAD 64
#define HID 512            // HEADS*DHEAD
#define QKV_ROWS 1536      // 3*HID
#define KV_ROWS 1024       // k,v only
#define CSPLIT 32          // n-splits for context partials

// ---------------------------------------------------------------------------
// Scratch (device globals; no allocation allowed)
// ---------------------------------------------------------------------------
__device__ __half g_kv[(size_t)BATCH * KV_ROWS * LDIM];     // fp16: k rows 0..511 (raw logits), v rows 512..1023
__device__ __half g_xt1[(size_t)BATCH * LDIM * CDIM];       // x^T, 1 fp16 limb
__device__ __half g_w1[(size_t)KV_ROWS * CDIM];             // W_kv, 1 limb
__device__ __half g_wqT1[(size_t)CDIM * HID];               // Wq^T limb 1
__device__ __half g_wqT2[(size_t)CDIM * HID];               // Wq^T limb 2
__device__ float g_rmax[(size_t)BATCH * HID];               // k row max
__device__ float g_rinv[(size_t)BATCH * HID];               // 1 / sum(exp(k-m))
__device__ float g_part[(size_t)CSPLIT * BATCH * HEADS * DHEAD * DHEAD];
__device__ float g_ctx[(size_t)BATCH * HEADS * DHEAD * DHEAD];
__device__ __half g_M1[(size_t)BATCH * HID * HID];          // M limbs
__device__ __half g_M2[(size_t)BATCH * HID * HID];
__device__ __half g_N1[(size_t)BATCH * HID * CDIM];         // N = M @ Wq limbs
__device__ __half g_N2[(size_t)BATCH * HID * CDIM];

// ---------------------------------------------------------------------------
// PTX helpers (baseline sm_103 — mma.sync fp16 only)
// ---------------------------------------------------------------------------
__device__ __forceinline__ uint32_t smem_to_u32(const void* smem_ptr) {
    uint32_t addr;
    asm("{ .reg .u64 tmp; cvta.to.shared.u64 tmp, %1; cvt.u32.u64 %0, tmp; }"
        : "=r"(addr) : "l"(smem_ptr));
    return addr;
}

#define SMEM_SWIZZLE_128B(byte_offset) \
    ((uint32_t)(byte_offset) ^ ((((uint32_t)(byte_offset)) >> 3) & 0x70u))

__device__ __forceinline__ void cp_async16(uint32_t dst, const void* src) {
    asm volatile("cp.async.cg.shared.global [%0], [%1], 16;"
                 :: "r"(dst), "l"(src) : "memory");
}
#define CP_ASYNC_COMMIT() asm volatile("cp.async.commit_group;" ::: "memory")
#define CP_ASYNC_WAIT(n)  asm volatile("cp.async.wait_group %0;" :: "n"(n) : "memory")

__device__ __forceinline__ void ldsm4(uint32_t* r, uint32_t addr) {
    asm volatile("ldmatrix.sync.aligned.m8n8.x4.shared.b16 {%0,%1,%2,%3}, [%4];"
                 : "=r"(r[0]), "=r"(r[1]), "=r"(r[2]), "=r"(r[3]) : "r"(addr));
}

__device__ __forceinline__ void mma_f16(float* c, const uint32_t* a, const uint32_t* b) {
    asm volatile(
        "mma.sync.aligned.m16n8k16.row.col.f32.f16.f16.f32 "
        "{%0,%1,%2,%3}, {%4,%5,%6,%7}, {%8,%9}, {%0,%1,%2,%3};"
        : "+f"(c[0]), "+f"(c[1]), "+f"(c[2]), "+f"(c[3])
        : "r"(a[0]), "r"(a[1]), "r"(a[2]), "r"(a[3]), "r"(b[0]), "r"(b[1]));
}

#define CHUNKS_PER_TILE 8    // K=512 / BK=64

// ---------------------------------------------------------------------------
// 1-term persistent fp16 GEMM: C = A1 @ B1^T (+bias), fp32 OR fp16 output.
// 256 threads (8 warps, 4x2 grid, warp tile 32x64), tile 128m x 128n.
// 3-stage cp.async ring (32KB/stage, 96KB/CTA -> 2 CTAs/SM).
// If Oh != null: write 1-limb fp16 output (__half2 stores) instead of fp32 C.
// ---------------------------------------------------------------------------
#define S1_STAGE 32768
#define S1_OFF_A 0
#define S1_OFF_B 16384
#define S1_SMEM (3 * S1_STAGE)

__global__ __launch_bounds__(256, 2)
void gemm1t_persistent(const __half* __restrict__ A1,
                       const __half* __restrict__ B1,
                       float* __restrict__ C,
                       int ntm, int ntn, int nb, int N, int K,
                       long long sA, long long sB, long long sC,
                       const float* __restrict__ bias,
                       __half* __restrict__ Oh)
{
    extern __shared__ char smem[];
    const uint32_t sbase = smem_to_u32(smem);

    const int tid = threadIdx.x;
    const int wid = tid >> 5;
    const int lane = tid & 31;
    const int warp_m = wid >> 1;       // 0..3 (32 rows each)
    const int warp_n = wid & 1;        // 0..1 (64 cols each)

    const int ntiles = ntm * ntn * nb;
    const int my_ntiles = (ntiles - (int)blockIdx.x + (int)gridDim.x - 1) / (int)gridDim.x;
    if (my_ntiles <= 0) return;
    const int my_nchunks = my_ntiles * CHUNKS_PER_TILE;

    auto load_chunk = [&](int k) {
        const int t = k >> 3;
        const int tile_lin = (int)blockIdx.x + t * (int)gridDim.x;
        if (tile_lin >= ntiles) { CP_ASYNC_COMMIT(); return; }
        const int nx = tile_lin % ntn;
        const int rest = tile_lin / ntn;
        const int my = rest % ntm;
        const int b = rest / ntm;
        const int bm = my << 7;
        const int bn = nx << 7;
        const int k0 = (k & 7) << 6;
        const __half* pA = A1 + (long long)b * sA;
        const __half* pB = B1 + (long long)b * sB;
        const uint32_t sb = sbase + (uint32_t)(k % 3) * S1_STAGE;
#pragma unroll
        for (int it = 0; it < 4; it++) {
            const int g = it * 256 + tid;
            const int row = g >> 3;
            const int gr = g & 7;
            const uint32_t sw = SMEM_SWIZZLE_128B(row * 128 + gr * 16);
            cp_async16(sb + S1_OFF_A + sw, pA + (long long)(bm + row) * K + k0 + gr * 8);
            cp_async16(sb + S1_OFF_B + sw, pB + (long long)(bn + row) * K + k0 + gr * 8);
        }
        CP_ASYNC_COMMIT();
    };

    float acc[2][8][4];
#pragma unroll
    for (int i = 0; i < 2; i++)
#pragma unroll
        for (int j = 0; j < 8; j++)
#pragma unroll
            for (int r = 0; r < 4; r++) acc[i][j][r] = 0.0f;

    load_chunk(0);
    load_chunk(1);

    for (int k = 0; k < my_nchunks; k++) {
        CP_ASYNC_WAIT(1);
        __syncthreads();          // single barrier per chunk (3-stage ring)

        const uint32_t sb = sbase + (uint32_t)(k % 3) * S1_STAGE;
#pragma unroll
        for (int ks = 0; ks < 4; ks++) {
            uint32_t b1r[16];
#pragma unroll
            for (int p = 0; p < 4; p++) {
                const int r = warp_n * 64 + p * 16 + ((lane >> 4) & 1) * 8 + (lane & 7);
                const int cb = ks * 32 + ((lane >> 3) & 1) * 16;
                ldsm4(b1r + p * 4, sb + S1_OFF_B + SMEM_SWIZZLE_128B(r * 128 + cb));
            }
#pragma unroll
            for (int i = 0; i < 2; i++) {
                const int r = warp_m * 32 + i * 16 + ((lane >> 3) & 1) * 8 + (lane & 7);
                const int cb = ks * 32 + ((lane >> 4) & 1) * 16;
                uint32_t a1[4];
                ldsm4(a1, sb + S1_OFF_A + SMEM_SWIZZLE_128B(r * 128 + cb));
#pragma unroll
                for (int j = 0; j < 8; j++)
                    mma_f16(acc[i][j], a1, b1r + (j >> 1) * 4 + (j & 1) * 2);
            }
        }

        load_chunk(k + 2);        // writes stage (k+2)%3 == (k-1)%3: safe

        if ((k & 7) == 7) {
            const int t = k >> 3;
            const int tile_lin = (int)blockIdx.x + t * (int)gridDim.x;
            const int nx = tile_lin % ntn;
            const int rest = tile_lin / ntn;
            const int my = rest % ntm;
            const int b = rest / ntm;
            const int bm = my << 7;
            const int bn = nx << 7;
            if (Oh == nullptr) {
                float* pC = C + (long long)b * sC;
#pragma unroll
                for (int i = 0; i < 2; i++) {
                    const int m0 = bm + warp_m * 32 + i * 16 + (lane >> 2);
                    const float bv0 = bias ? bias[m0] : 0.0f;
                    const float bv1 = bias ? bias[m0 + 8] : 0.0f;
#pragma unroll
                    for (int j = 0; j < 8; j++) {
                        const int n0 = bn + warp_n * 64 + j * 8 + (lane & 3) * 2;
                        float2 v0, v1;
                        v0.x = acc[i][j][0] + bv0;  v0.y = acc[i][j][1] + bv0;
                        v1.x = acc[i][j][2] + bv1;  v1.y = acc[i][j][3] + bv1;
                        *(float2*)(pC + (long long)m0 * N + n0) = v0;
                        *(float2*)(pC + (long long)(m0 + 8) * N + n0) = v1;
                        acc[i][j][0] = 0.0f; acc[i][j][1] = 0.0f;
                        acc[i][j][2] = 0.0f; acc[i][j][3] = 0.0f;
                    }
                }
            } else {
                __half* pH = Oh + (long long)b * sC;
#pragma unroll
                for (int i = 0; i < 2; i++) {
                    const int m0 = bm + warp_m * 32 + i * 16 + (lane >> 2);
#pragma unroll
                    for (int j = 0; j < 8; j++) {
                        const int n0 = bn + warp_n * 64 + j * 8 + (lane & 3) * 2;
                        *(__half2*)(pH + (long long)m0 * N + n0) =
                            __floats2half2_rn(acc[i][j][0], acc[i][j][1]);
                        *(__half2*)(pH + (long long)(m0 + 8) * N + n0) =
                            __floats2half2_rn(acc[i][j][2], acc[i][j][3]);
                        acc[i][j][0] = 0.0f; acc[i][j][1] = 0.0f;
                        acc[i][j][2] = 0.0f; acc[i][j][3] = 0.0f;
                    }
                }
            }
        }
    }
}

// ---------------------------------------------------------------------------
// General multi-limb persistent GEMM (tiny N = M @ Wq only, 3-term,
// 2-limb fp16 output). 128 threads, tile 64x128, 2-stage.
// ---------------------------------------------------------------------------
#define STAGE_BYTES 49152
#define OFF_A1 0
#define OFF_A2 8192
#define OFF_B1 16384
#define OFF_B2 32768
#define GEMM_SMEM (2 * STAGE_BYTES)

__global__ __launch_bounds__(128, 2)
void mma_gemm_persistent(const __half* __restrict__ A1,
                         const __half* __restrict__ A2,
                         const __half* __restrict__ B1,
                         const __half* __restrict__ B2,
                         float* __restrict__ C,
                         int ntm, int ntn, int nb, int N, int K,
                         long long sA, long long sB, long long sC,
                         const float* __restrict__ bias,
                         __half* __restrict__ O1,
                         __half* __restrict__ O2)
{
    extern __shared__ char smem[];
    const uint32_t sbase = smem_to_u32(smem);

    const int tid = threadIdx.x;
    const int wid = tid >> 5;
    const int lane = tid & 31;
    const int warp_m = wid >> 1;
    const int warp_n = wid & 1;
    const bool has_a2 = (A2 != nullptr);
    const bool has_b2 = (B2 != nullptr);

    const int ntiles = ntm * ntn * nb;
    const int my_ntiles = (ntiles - (int)blockIdx.x + (int)gridDim.x - 1) / (int)gridDim.x;
    if (my_ntiles <= 0) return;
    const int my_nchunks = my_ntiles * CHUNKS_PER_TILE;

    auto load_chunk = [&](int k) {
        const int t = k >> 3;
        const int tile_lin = (int)blockIdx.x + t * (int)gridDim.x;
        if (tile_lin >= ntiles) { CP_ASYNC_COMMIT(); return; }
        const int nx = tile_lin % ntn;
        const int rest = tile_lin / ntn;
        const int my = rest % ntm;
        const int b = rest / ntm;
        const int bm = my << 6;
        const int bn = nx << 7;
        const int k0 = (k & 7) << 6;
        const __half* pA1 = A1 + (long long)b * sA;
        const __half* pB1 = B1 + (long long)b * sB;
        const uint32_t sb = sbase + (uint32_t)(k & 1) * STAGE_BYTES;
#pragma unroll
        for (int it = 0; it < 4; it++) {
            const int g = it * 128 + tid;
            const int row = g >> 3;
            const int gr = g & 7;
            const uint32_t sw = SMEM_SWIZZLE_128B(row * 128 + gr * 16);
            cp_async16(sb + OFF_A1 + sw, pA1 + (long long)(bm + row) * K + k0 + gr * 8);
        }
        if (has_a2) {
            const __half* pA2 = A2 + (long long)b * sA;
#pragma unroll
            for (int it = 0; it < 4; it++) {
                const int g = it * 128 + tid;
                const int row = g >> 3;
                const int gr = g & 7;
                const uint32_t sw = SMEM_SWIZZLE_128B(row * 128 + gr * 16);
                cp_async16(sb + OFF_A2 + sw, pA2 + (long long)(bm + row) * K + k0 + gr * 8);
            }
        }
#pragma unroll
        for (int it = 0; it < 8; it++) {
            const int g = it * 128 + tid;
            const int row = g >> 3;
            const int gr = g & 7;
            const uint32_t sw = SMEM_SWIZZLE_128B(row * 128 + gr * 16);
            cp_async16(sb + OFF_B1 + sw, pB1 + (long long)(bn + row) * K + k0 + gr * 8);
        }
        if (has_b2) {
            const __half* pB2 = B2 + (long long)b * sB;
#pragma unroll
            for (int it = 0; it < 8; it++) {
                const int g = it * 128 + tid;
                const int row = g >> 3;
                const int gr = g & 7;
                const uint32_t sw = SMEM_SWIZZLE_128B(row * 128 + gr * 16);
                cp_async16(sb + OFF_B2 + sw, pB2 + (long long)(bn + row) * K + k0 + gr * 8);
            }
        }
        CP_ASYNC_COMMIT();
    };

    float acc[2][8][4];
#pragma unroll
    for (int i = 0; i < 2; i++)
#pragma unroll
        for (int j = 0; j < 8; j++)
#pragma unroll
            for (int r = 0; r < 4; r++) acc[i][j][r] = 0.0f;

    load_chunk(0);
    load_chunk(1);

    for (int k = 0; k < my_nchunks; k++) {
        CP_ASYNC_WAIT(1);
        __syncthreads();

        const uint32_t sb = sbase + (uint32_t)(k & 1) * STAGE_BYTES;
#pragma unroll
        for (int ks = 0; ks < 4; ks++) {
            uint32_t b1r[16];
#pragma unroll
            for (int p = 0; p < 4; p++) {
                const int r = warp_n * 64 + p * 16 + ((lane >> 4) & 1) * 8 + (lane & 7);
                const int cb = ks * 32 + ((lane >> 3) & 1) * 16;
                ldsm4(b1r + p * 4, sb + OFF_B1 + SMEM_SWIZZLE_128B(r * 128 + cb));
            }
            uint32_t b2r[16];
            if (has_b2) {
#pragma unroll
                for (int p = 0; p < 4; p++) {
                    const int r = warp_n * 64 + p * 16 + ((lane >> 4) & 1) * 8 + (lane & 7);
                    const int cb = ks * 32 + ((lane >> 3) & 1) * 16;
                    ldsm4(b2r + p * 4, sb + OFF_B2 + SMEM_SWIZZLE_128B(r * 128 + cb));
                }
            }
#pragma unroll
            for (int i = 0; i < 2; i++) {
                const int r = warp_m * 32 + i * 16 + ((lane >> 3) & 1) * 8 + (lane & 7);
                const int cb = ks * 32 + ((lane >> 4) & 1) * 16;
                const uint32_t adr = sb + OFF_A1 + SMEM_SWIZZLE_128B(r * 128 + cb);
                uint32_t a1[4];
                ldsm4(a1, adr);
#pragma unroll
                for (int j = 0; j < 8; j++)
                    mma_f16(acc[i][j], a1, b1r + (j >> 1) * 4 + (j & 1) * 2);
                if (has_a2) {
                    uint32_t a2[4];
                    ldsm4(a2, adr + (OFF_A2 - OFF_A1));
#pragma unroll
                    for (int j = 0; j < 8; j++)
                        mma_f16(acc[i][j], a2, b1r + (j >> 1) * 4 + (j & 1) * 2);
                }
                if (has_b2) {
#pragma unroll
                    for (int j = 0; j < 8; j++)
                        mma_f16(acc[i][j], a1, b2r + (j >> 1) * 4 + (j & 1) * 2);
                }
            }
        }
        __syncthreads();
        load_chunk(k + 2);

        if ((k & 7) == 7) {
            const int t = k >> 3;
            const int tile_lin = (int)blockIdx.x + t * (int)gridDim.x;
            const int nx = tile_lin % ntn;
            const int rest = tile_lin / ntn;
            const int my = rest % ntm;
            const int b = rest / ntm;
            const int bm = my << 6;
            const int bn = nx << 7;
            if (O1 == nullptr) {
                float* pC = C + (long long)b * sC;
#pragma unroll
                for (int i = 0; i < 2; i++) {
                    const int m0 = bm + warp_m * 32 + i * 16 + (lane >> 2);
                    const float bv0 = bias ? bias[m0] : 0.0f;
                    const float bv1 = bias ? bias[m0 + 8] : 0.0f;
#pragma unroll
                    for (int j = 0; j < 8; j++) {
                        const int n0 = bn + warp_n * 64 + j * 8 + (lane & 3) * 2;
                        float2 v0, v1;
                        v0.x = acc[i][j][0] + bv0;  v0.y = acc[i][j][1] + bv0;
                        v1.x = acc[i][j][2] + bv1;  v1.y = acc[i][j][3] + bv1;
                        *(float2*)(pC + (long long)m0 * N + n0) = v0;
                        *(float2*)(pC + (long long)(m0 + 8) * N + n0) = v1;
                        acc[i][j][0] = 0.0f; acc[i][j][1] = 0.0f;
                        acc[i][j][2] = 0.0f; acc[i][j][3] = 0.0f;
                    }
                }
            } else {
                __half* p1 = O1 + (long long)b * sC;
                __half* p2 = O2 + (long long)b * sC;
#pragma unroll
                for (int i = 0; i < 2; i++) {
                    const int m0 = bm + warp_m * 32 + i * 16 + (lane >> 2);
#pragma unroll
                    for (int j = 0; j < 8; j++) {
                        const int n0 = bn + warp_n * 64 + j * 8 + (lane & 3) * 2;
#pragma unroll
                        for (int r = 0; r < 4; r++) {
                            const int mm = m0 + (r >> 1) * 8;
                            const int nn = n0 + (r & 1);
                            const float v = acc[i][j][r];
                            const __half h1 = __float2half_rn(v);
                            p1[(long long)mm * N + nn] = h1;
                            p2[(long long)mm * N + nn] = __float2half_rn(v - __half2float(h1));
                            acc[i][j][r] = 0.0f;
                        }
                    }
                }
            }
        }
    }
}

// ---------------------------------------------------------------------------
// Transpose + fp16 convert (1 limb): in fp32 [R, L] -> out [L, R]
// ---------------------------------------------------------------------------
__global__ __launch_bounds__(256) void transpose_cvt1_kernel(
    const float* __restrict__ in, __half* __restrict__ out,
    int R, int L, long long inStride, long long outStride)
{
    const int b = blockIdx.z;
    in += (long long)b * inStride;
    out += (long long)b * outStride;

    __shared__ float t[32][33];
    const int r0 = blockIdx.y * 32;
    const int c0 = blockIdx.x * 32;
    const int tx = threadIdx.x & 31;
    const int ty = threadIdx.x >> 5;

#pragma unroll
    for (int i = 0; i < 4; i++)
        t[ty + i * 8][tx] = in[(long long)(r0 + ty + i * 8) * L + c0 + tx];
    __syncthreads();
#pragma unroll
    for (int i = 0; i < 4; i++) {
        const float v = t[tx][ty + i * 8];
        out[(long long)(c0 + ty + i * 8) * R + r0 + tx] = __float2half_rn(v);
    }
}

// Transpose + fp16 2-limb split: in fp32 [R, L] -> limbs [L, R]
__global__ __launch_bounds__(256) void transpose_cvt2_kernel(
    const float* __restrict__ in,
    __half* __restrict__ o1, __half* __restrict__ o2, int R, int L)
{
    __shared__ float t[32][33];
    const int r0 = blockIdx.y * 32;
    const int c0 = blockIdx.x * 32;
    const int tx = threadIdx.x & 31;
    const int ty = threadIdx.x >> 5;

#pragma unroll
    for (int i = 0; i < 4; i++)
        t[ty + i * 8][tx] = in[(long long)(r0 + ty + i * 8) * L + c0 + tx];
    __syncthreads();
#pragma unroll
    for (int i = 0; i < 4; i++) {
        const float v = t[tx][ty + i * 8];
        const __half h1 = __float2half_rn(v);
        const long long o = (long long)(c0 + ty + i * 8) * R + r0 + tx;
        o1[o] = h1;
        o2[o] = __float2half_rn(v - __half2float(h1));
    }
}

// Plain fp16 convert (1 limb)
__global__ __launch_bounds__(256) void cvt1_kernel(
    const float* __restrict__ in, __half* __restrict__ o1, int n)
{
    const int i = blockIdx.x * blockDim.x + threadIdx.x;
    if (i < n) o1[i] = __float2half_rn(in[i]);
}

// ---------------------------------------------------------------------------
// Row stats for softmax (READ-ONLY, fp16 input): max + 1/sum(exp(k-m)).
// ---------------------------------------------------------------------------
__global__ __launch_bounds__(256) void rowstat_kernel()
{
    const int row = blockIdx.x;           // 0..BATCH*512-1
    const int b = row >> 9;
    const int r = row & 511;
    const __half* p = g_kv + (long long)b * KV_ROWS * LDIM + (long long)r * LDIM;

    const int tid = threadIdx.x;
    __shared__ float red[256];

    // 4096 halves per row; each thread loads 2 x uint4 = 16 halves
    uint4 u0 = ((const uint4*)p)[tid];
    uint4 u1 = ((const uint4*)p)[256 + tid];

    float f[16];
    {
        const uint32_t* w = &u0.x;
#pragma unroll
        for (int i = 0; i < 4; i++) {
            float2 t = __half22float2(*(const __half2*)&w[i]);
            f[i * 2] = t.x; f[i * 2 + 1] = t.y;
        }
        const uint32_t* w2 = &u1.x;
#pragma unroll
        for (int i = 0; i < 4; i++) {
            float2 t = __half22float2(*(const __half2*)&w2[i]);
            f[8 + i * 2] = t.x; f[8 + i * 2 + 1] = t.y;
        }
    }

    float vmax = -1e30f;
#pragma unroll
    for (int i = 0; i < 16; i++) vmax = fmaxf(vmax, f[i]);
    red[tid] = vmax;
    __syncthreads();
    for (int s = 128; s > 0; s >>= 1) {
        if (tid < s) red[tid] = fmaxf(red[tid], red[tid + s]);
        __syncthreads();
    }
    vmax = red[0];
    __syncthreads();

    float lsum = 0.0f;
#pragma unroll
    for (int i = 0; i < 16; i++) lsum += expf(f[i] - vmax);
    red[tid] = lsum;
    __syncthreads();
    for (int s = 128; s > 0; s >>= 1) {
        if (tid < s) red[tid] += red[tid + s];
        __syncthreads();
    }
    if (tid == 0) {
        g_rmax[row] = vmax;
        g_rinv[row] = 1.0f / red[0];
    }
}

// ---------------------------------------------------------------------------
// Context partials: fp16 k/v loads, softmax applied INLINE on k load.
// ---------------------------------------------------------------------------
__global__ __launch_bounds__(256) void context_partial_kernel()
{
    const int split = blockIdx.x;
    const int bh = blockIdx.y;
    const int b = bh >> 3, h = bh & 7;

    const __half* kbase = g_kv + (long long)b * KV_ROWS * LDIM + (long long)(h * DHEAD) * LDIM;
    const __half* vbase = g_kv + (long long)b * KV_ROWS * LDIM + (long long)(HID + h * DHEAD) * LDIM;

    __shared__ float Ks[64][65];
    __shared__ float Vs[64][65];
    __shared__ float sm_m[64], sm_i[64];

    const int tid = threadIdx.x;
    if (tid < 64) {
        const int row = b * HID + h * DHEAD + tid;
        sm_m[tid] = g_rmax[row];
        sm_i[tid] = g_rinv[row];
    }
    __syncthreads();

    const int td = (tid >> 4) * 4;
    const int te = (tid & 15) * 4;

    float acc[4][4];
#pragma unroll
    for (int i = 0; i < 4; i++)
#pragma unroll
        for (int j = 0; j < 4; j++) acc[i][j] = 0.0f;

    const int chunk = LDIM / CSPLIT;
    for (int sub = 0; sub < chunk / 64; sub++) {
        const int n0 = split * chunk + sub * 64;
        for (int i = tid; i < 1024; i += 256) {
            const int r = i >> 4, c = (i & 15) * 4;
            const float m = sm_m[r], s = sm_i[r];
            uint2 kr = *(const uint2*)(kbase + (long long)r * LDIM + n0 + c);
            float2 k0 = __half22float2(*(const __half2*)&kr.x);
            float2 k1 = __half22float2(*(const __half2*)&kr.y);
            Ks[r][c]     = expf(k0.x - m) * s;
            Ks[r][c + 1] = expf(k0.y - m) * s;
            Ks[r][c + 2] = expf(k1.x - m) * s;
            Ks[r][c + 3] = expf(k1.y - m) * s;
            uint2 vr = *(const uint2*)(vbase + (long long)r * LDIM + n0 + c);
            float2 v0 = __half22float2(*(const __half2*)&vr.x);
            float2 v1 = __half22float2(*(const __half2*)&vr.y);
            Vs[r][c] = v0.x; Vs[r][c + 1] = v0.y; Vs[r][c + 2] = v1.x; Vs[r][c + 3] = v1.y;
        }
        __syncthreads();

#pragma unroll 8
        for (int n = 0; n < 64; n++) {
            float kr[4], vr[4];
#pragma unroll
            for (int i = 0; i < 4; i++) kr[i] = Ks[td + i][n];
#pragma unroll
            for (int j = 0; j < 4; j++) vr[j] = Vs[te + j][n];
#pragma unroll
            for (int i = 0; i < 4; i++)
#pragma unroll
                for (int j = 0; j < 4; j++)
                    acc[i][j] = fmaf(kr[i], vr[j], acc[i][j]);
        }
        __syncthreads();
    }

    float* pout = g_part + ((long long)split * 64 + bh) * (DHEAD * DHEAD);
#pragma unroll
    for (int i = 0; i < 4; i++)
#pragma unroll
        for (int j = 0; j < 4; j++)
            pout[(td + i) * DHEAD + (te + j)] = acc[i][j];
}

__global__ __launch_bounds__(256) void reduce_ctx_kernel()
{
    const int i = blockIdx.x * blockDim.x + threadIdx.x;
    const int total = BATCH * HEADS * DHEAD * DHEAD;
    if (i < total) {
        float s = 0.0f;
#pragma unroll
        for (int sp = 0; sp < CSPLIT; sp++)
            s += g_part[(long long)sp * total + i];
        g_ctx[i] = s;
    }
}

// fold: writes 2-limb fp16 M directly
__global__ __launch_bounds__(256) void fold_kernel(const float* __restrict__ w_out)
{
    const int oc = blockIdx.x;
    const int bh = blockIdx.y;
    const int b = bh >> 3, h = bh & 7;

    __shared__ float cs[64][65];
    __shared__ float ws[64][65];

    const int tid = threadIdx.x;
    for (int i = tid; i < 4096; i += 256) {
        const int d = i >> 6, e = i & 63;
        cs[d][e] = g_ctx[((long long)bh * 64 + d) * 64 + e];
    }
    for (int i = tid; i < 4096; i += 256) {
        const int r = i >> 6, e = i & 63;
        ws[r][e] = w_out[(long long)(oc * 64 + r) * CDIM + h * 64 + e];
    }
    __syncthreads();

    const int d = tid & 63;
    const int r0 = (tid >> 6) * 16;
    for (int rr = 0; rr < 16; rr++) {
        float s = 0.0f;
#pragma unroll 8
        for (int e = 0; e < 64; e++)
            s = fmaf(ws[r0 + rr][e], cs[d][e], s);
        const long long o = ((long long)b * HID + oc * 64 + r0 + rr) * HID + h * 64 + d;
        const __half h1 = __float2half_rn(s);
        g_M1[o] = h1;
        g_M2[o] = __float2half_rn(s - __half2float(h1));
    }
}

// ---------------------------------------------------------------------------
extern "C" void kernel_launch(void* const* d_in, const int* in_sizes, int n_in,
                              void* d_out, int out_size)
{
    const float* x     = (const float*)d_in[0];   // [8, 512, 4096]
    const float* w_qkv = (const float*)d_in[1];   // [1536, 512]
    const float* w_out = (const float*)d_in[2];   // [512, 512]
    const float* b_out = (const float*)d_in[3];   // [512]
    float* out = (float*)d_out;                   // [8, 512, 4096]

    __half *p_kv, *p_xt1, *p_w1, *p_wqT1, *p_wqT2, *p_M1, *p_M2, *p_N1, *p_N2;
    cudaGetSymbolAddress((void**)&p_kv, g_kv);
    cudaGetSymbolAddress((void**)&p_xt1, g_xt1);
    cudaGetSymbolAddress((void**)&p_w1, g_w1);
    cudaGetSymbolAddress((void**)&p_wqT1, g_wqT1);
    cudaGetSymbolAddress((void**)&p_wqT2, g_wqT2);
    cudaGetSymbolAddress((void**)&p_M1, g_M1);
    cudaGetSymbolAddress((void**)&p_M2, g_M2);
    cudaGetSymbolAddress((void**)&p_N1, g_N1);
    cudaGetSymbolAddress((void**)&p_N2, g_N2);

    int nsm = 148;
    cudaDeviceGetAttribute(&nsm, cudaDevAttrMultiProcessorCount, 0);

    cudaFuncSetAttribute(gemm1t_persistent,
                         cudaFuncAttributeMaxDynamicSharedMemorySize, S1_SMEM);
    cudaFuncSetAttribute(mma_gemm_persistent,
                         cudaFuncAttributeMaxDynamicSharedMemorySize, GEMM_SMEM);

    // 0) fp16 converts: W_kv (1 limb), x^T (1 limb), Wq^T (2 limbs)
    cvt1_kernel<<<(KV_ROWS * CDIM + 255) / 256, 256>>>(
        w_qkv + (size_t)HID * CDIM, p_w1, KV_ROWS * CDIM);
    transpose_cvt1_kernel<<<dim3(LDIM / 32, CDIM / 32, BATCH), 256>>>(
        x, p_xt1, CDIM, LDIM, (long long)CDIM * LDIM, (long long)LDIM * CDIM);
    transpose_cvt2_kernel<<<dim3(CDIM / 32, HID / 32, 1), 256>>>(
        w_qkv, p_wqT1, p_wqT2, HID, CDIM);

    // 1) kv = W_kv @ x  (1-term fp16, fp16 output directly)
    gemm1t_persistent<<<2 * nsm, 256, S1_SMEM>>>(
        p_w1, p_xt1, nullptr,
        KV_ROWS / 128, LDIM / 128, BATCH, LDIM, CDIM,
        0LL, (long long)LDIM * CDIM, (long long)KV_ROWS * LDIM, nullptr,
        p_kv);

    // 2) softmax row stats (fp16 reads; k stays raw, applied inline below)
    rowstat_kernel<<<BATCH * HID, 256>>>();

    // 3) context partials (fp16 loads, inline softmax) + deterministic reduce
    context_partial_kernel<<<dim3(CSPLIT, BATCH * HEADS), 256>>>();
    {
        const int total = BATCH * HEADS * DHEAD * DHEAD;
        reduce_ctx_kernel<<<(total + 255) / 256, 256>>>();
    }

    // 4) fold w_out with context -> 2-limb fp16 M
    fold_kernel<<<dim3(8, BATCH * HEADS), 256>>>(w_out);

    // 5) N = M @ Wq  (3-term fp16; tiny, keeps this link near-exact)
    mma_gemm_persistent<<<2 * nsm, 128, GEMM_SMEM>>>(
        p_M1, p_M2, p_wqT1, p_wqT2, nullptr,
        HID / 64, CDIM / 128, BATCH, CDIM, HID,
        (long long)HID * HID, 0LL, (long long)HID * CDIM, nullptr,
        p_N1, p_N2);

    // 6) out = N @ x + b_out  (1-term fp16, fp32 output)
    gemm1t_persistent<<<2 * nsm, 256, S1_SMEM>>>(
        p_N1, p_xt1, out,
        HID / 128, LDIM / 128, BATCH, LDIM, CDIM,
        (long long)HID * CDIM, (long long)LDIM * CDIM, (long long)HID * LDIM, b_out,
        nullptr);
}